// round 13
// baseline (speedup 1.0000x reference)
#include <cuda_runtime.h>
#include <cuda_fp16.h>
#include <cstdint>

#define BB   4
#define SEQ  8192
#define DIM  256
#define NH   8
#define HD   32
#define MTOT (BB*SEQ)        // 32768
#define CCH  32

// ===================== scratch (device globals) =====================
__device__ __half g_a[7ull * MTOT * 256];        // fp16 activations: q_in, k2..k4, v2..v4
__device__ __half g_q16[(size_t)MTOT * 768];     // fp16 expq = exp(q)/32
__device__ __half g_w[786432];                   // fp16 weights: wq|wk,wv|wf(256x768)
__device__ __half g_E[4ull * 256 * 768];         // per-batch effective final weights (inv folded)
__device__ __half g_k16[3ull * MTOT * DIM];
__device__ __half g_v16[3ull * MTOT * DIM];
__device__ float g_ctxp[3ull * BB * NH * CCH * HD * HD];
__device__ float g_qs  [BB * 768];               // 1 / sum(exp(q)/32)
__device__ float g_qsp [256 * 768];              // per-row-block column partials

// ===================== helpers =====================
__device__ __forceinline__ uint32_t smem_u32(const void* p){
    uint32_t a;
    asm("{ .reg .u64 t; cvta.to.shared.u64 t, %1; cvt.u32.u64 %0, t; }" : "=r"(a) : "l"(p));
    return a;
}
__device__ __forceinline__ void cp16(uint32_t dst, const void* src){
    asm volatile("cp.async.cg.shared.global [%0], [%1], 16;" :: "r"(dst), "l"(src) : "memory");
}
__device__ __forceinline__ void cp_commit(){ asm volatile("cp.async.commit_group;" ::: "memory"); }
__device__ __forceinline__ void cp_wait1(){ asm volatile("cp.async.wait_group 1;" ::: "memory"); }
__device__ __forceinline__ void cp_wait0(){ asm volatile("cp.async.wait_group 0;" ::: "memory"); }

__device__ __forceinline__ void ldsm4(uint32_t& r0, uint32_t& r1, uint32_t& r2, uint32_t& r3, uint32_t addr){
    asm volatile("ldmatrix.sync.aligned.m8n8.x4.shared.b16 {%0,%1,%2,%3}, [%4];"
        : "=r"(r0), "=r"(r1), "=r"(r2), "=r"(r3) : "r"(addr));
}
__device__ __forceinline__ void mma16816(float* d, const uint32_t* a, const uint32_t* b){
    asm volatile("mma.sync.aligned.m16n8k16.row.col.f32.f16.f16.f32 "
        "{%0,%1,%2,%3}, {%4,%5,%6,%7}, {%8,%9}, {%0,%1,%2,%3};"
        : "+f"(d[0]), "+f"(d[1]), "+f"(d[2]), "+f"(d[3])
        : "r"(a[0]), "r"(a[1]), "r"(a[2]), "r"(a[3]), "r"(b[0]), "r"(b[1]));
}
// fp16-accumulate variant: D(2 regs = 4 halves) += A*B
__device__ __forceinline__ void mma16816h(uint32_t* d, const uint32_t* a, const uint32_t* b){
    asm volatile("mma.sync.aligned.m16n8k16.row.col.f16.f16.f16.f16 "
        "{%0,%1}, {%2,%3,%4,%5}, {%6,%7}, {%0,%1};"
        : "+r"(d[0]), "+r"(d[1])
        : "r"(a[0]), "r"(a[1]), "r"(a[2]), "r"(a[3]), "r"(b[0]), "r"(b[1]));
}

// ===================== GEMM core: 128x128 CTA tile, fp32 acc (R9 config) =====
#define STG_BYTES 20480
#define GEMM_SMEM (3 * STG_BYTES)

#define GEMM_BODY(A, lda, B, ldb, nkc, ROW0, COL0)                              \
    const int lane = tid & 31, wid = tid >> 5;                                  \
    const int wm = wid >> 2, wn = wid & 3;                                      \
    const int row0 = (ROW0);                                                    \
    const int col0 = (COL0);                                                    \
    float acc[4][4][4];                                                         \
    _Pragma("unroll") for (int i = 0; i < 4; i++)                               \
    _Pragma("unroll") for (int j = 0; j < 4; j++)                               \
    _Pragma("unroll") for (int v = 0; v < 4; v++) acc[i][j][v] = 0.f;           \
    const uint32_t smem_base = smem_u32(smem);                                  \
    const int ch0 = tid * 2;                                                    \
    auto prefetch = [&](int kc) {                                               \
        int s = kc % 3;                                                         \
        uint32_t As = smem_base + s * STG_BYTES;                                \
        uint32_t Bs = As + 10240;                                               \
        _Pragma("unroll") for (int t = 0; t < 2; t++) {                         \
            int ch = ch0 + t;                                                   \
            int r = ch >> 2, c = ch & 3;                                        \
            cp16(As + r * 80 + c * 16, A + (size_t)(row0 + r) * lda + kc * 32 + c * 8); \
            cp16(Bs + r * 80 + c * 16, B + (size_t)(col0 + r) * ldb + kc * 32 + c * 8); \
        }                                                                       \
        cp_commit();                                                            \
    };                                                                          \
    prefetch(0);                                                                \
    if (nkc > 1) prefetch(1);                                                   \
    const int arow = lane & 15, acolh = (lane >> 4) * 8;                        \
    const int bn   = (lane & 7) + (lane >> 4) * 8;                              \
    const int bkh  = ((lane >> 3) & 1) * 8;                                     \
    for (int kc = 0; kc < nkc; kc++) {                                          \
        if (kc + 1 < nkc) cp_wait1(); else cp_wait0();                          \
        __syncthreads();                                                        \
        if (kc + 2 < nkc) prefetch(kc + 2);                                     \
        int s = kc % 3;                                                         \
        uint32_t As = smem_base + s * STG_BYTES;                                \
        uint32_t Bs = As + 10240;                                               \
        _Pragma("unroll") for (int kk = 0; kk < 32; kk += 16) {                 \
            uint32_t af[4][4];                                                  \
            _Pragma("unroll") for (int i = 0; i < 4; i++) {                     \
                uint32_t addr = As + (wm * 64 + i * 16 + arow) * 80 + (kk + acolh) * 2; \
                ldsm4(af[i][0], af[i][1], af[i][2], af[i][3], addr);            \
            }                                                                   \
            uint32_t bf[4][2];                                                  \
            _Pragma("unroll") for (int jp = 0; jp < 2; jp++) {                  \
                uint32_t addr = Bs + (wn * 32 + jp * 16 + bn) * 80 + (kk + bkh) * 2; \
                ldsm4(bf[2*jp][0], bf[2*jp][1], bf[2*jp+1][0], bf[2*jp+1][1], addr); \
            }                                                                   \
            _Pragma("unroll") for (int i = 0; i < 4; i++)                       \
            _Pragma("unroll") for (int j = 0; j < 4; j++)                       \
                mma16816(acc[i][j], af[i], bf[j]);                              \
        }                                                                       \
    }

// qall GEMM with fused exp + column partial sums (R9 config).
__global__ void __launch_bounds__(256, 2)
gemm_expq(const __half* __restrict__ Ag, int lda,
          const __half* __restrict__ Bg, int ldb,
          const float* __restrict__ bias, __half* __restrict__ C, int N, int KH)
{
    extern __shared__ __align__(16) char smem[];
    const int tid = threadIdx.x;
    GEMM_BODY(Ag, lda, Bg, ldb, KH, blockIdx.y * 128, blockIdx.x * 128)

    __syncthreads();
    float* red = reinterpret_cast<float*>(smem);      // [16][128]
    const int g = lane >> 2, tg = lane & 3;
    float bb0[4], bb1[4];
#pragma unroll
    for (int j = 0; j < 4; j++) {
        int c = col0 + wn * 32 + j * 8 + 2 * tg;
        bb0[j] = bias[c]; bb1[j] = bias[c + 1];
    }
    float cs0[4] = {0.f,0.f,0.f,0.f}, cs1[4] = {0.f,0.f,0.f,0.f};
#pragma unroll
    for (int i = 0; i < 4; i++) {
        int r = row0 + wm * 64 + i * 16 + g;
#pragma unroll
        for (int j = 0; j < 4; j++) {
            int c = col0 + wn * 32 + j * 8 + 2 * tg;
            float e0 = __expf(acc[i][j][0] + bb0[j]) * 0.03125f;
            float e1 = __expf(acc[i][j][1] + bb1[j]) * 0.03125f;
            float e2 = __expf(acc[i][j][2] + bb0[j]) * 0.03125f;
            float e3 = __expf(acc[i][j][3] + bb1[j]) * 0.03125f;
            *reinterpret_cast<__half2*>(C + (size_t)r * N + c)       = __floats2half2_rn(e0, e1);
            *reinterpret_cast<__half2*>(C + (size_t)(r + 8) * N + c) = __floats2half2_rn(e2, e3);
            cs0[j] += e0 + e2;
            cs1[j] += e1 + e3;
        }
    }
#pragma unroll
    for (int j = 0; j < 4; j++) {
        int lc = wn * 32 + j * 8 + 2 * tg;
        red[(wm * 8 + g) * 128 + lc]     = cs0[j];
        red[(wm * 8 + g) * 128 + lc + 1] = cs1[j];
    }
    __syncthreads();
    if (tid < 128) {
        float s = 0.f;
#pragma unroll
        for (int u = 0; u < 16; u++) s += red[u * 128 + tid];
        g_qsp[(size_t)blockIdx.y * 768 + col0 + tid] = s;
    }
}

// fp32-output GEMM with per-batch B (final): B += (blockIdx.y>>6)*bstride
__global__ void __launch_bounds__(256, 2)
gemm_f32out(const __half* __restrict__ Ag, int lda,
            const __half* __restrict__ Bg0, int ldb, size_t bstride,
            const float* __restrict__ bias, float* __restrict__ C, int N, int KH)
{
    extern __shared__ __align__(16) char smem[];
    const int tid = threadIdx.x;
    const __half* Bg = Bg0 + (size_t)(blockIdx.y >> 6) * bstride;
    GEMM_BODY(Ag, lda, Bg, ldb, KH, blockIdx.y * 128, blockIdx.x * 128)

    const int g = lane >> 2, tg = lane & 3;
    float2 bb[4];
#pragma unroll
    for (int j = 0; j < 4; j++) {
        int c = col0 + wn * 32 + j * 8 + 2 * tg;
        bb[j] = make_float2(bias[c], bias[c + 1]);
    }
#pragma unroll
    for (int i = 0; i < 4; i++) {
        int r = row0 + wm * 64 + i * 16 + g;
#pragma unroll
        for (int j = 0; j < 4; j++) {
            int c = col0 + wn * 32 + j * 8 + 2 * tg;
            *reinterpret_cast<float2*>(C + (size_t)r * N + c) =
                make_float2(acc[i][j][0] + bb[j].x, acc[i][j][1] + bb[j].y);
            *reinterpret_cast<float2*>(C + (size_t)(r + 8) * N + c) =
                make_float2(acc[i][j][2] + bb[j].x, acc[i][j][3] + bb[j].y);
        }
    }
}

// ===================== k/v GEMM: fp16-acc, 128 threads, warp tile 64x64 ======
// z = 0..5 -> branch = z%3, kv = z/3; fp16 output. 24% less smem traffic/MMA.
__global__ void __launch_bounds__(128)
gemm_kv(const __half* __restrict__ abuf, const __half* __restrict__ wkv,
        const float* __restrict__ bk, const float* __restrict__ bv)
{
    extern __shared__ __align__(16) char smem[];
    const int tid = threadIdx.x;
    const int z = blockIdx.z;
    const int branch = z % 3, kv = z / 3;
    const __half* A = abuf + (size_t)(1 + branch + 3 * kv) * MTOT * 256;
    const __half* B = wkv + (size_t)(3 * kv + branch) * 65536;
    const float* bias = (kv ? bv : bk) + branch * 256;
    __half* C = (kv ? g_v16 : g_k16) + (size_t)branch * MTOT * 256;

    const int lane = tid & 31, wid = tid >> 5;
    const int wm = wid >> 1, wn = wid & 1;           // warp grid 2x2
    const int row0 = blockIdx.y * 128;
    const int col0 = blockIdx.x * 128;

    uint32_t acc[4][8][2];
#pragma unroll
    for (int i = 0; i < 4; i++)
#pragma unroll
        for (int j = 0; j < 8; j++) { acc[i][j][0] = 0u; acc[i][j][1] = 0u; }

    const uint32_t smem_base = smem_u32(smem);

    auto prefetch = [&](int kc) {
        int s = kc % 3;
        uint32_t As = smem_base + s * STG_BYTES;
        uint32_t Bs = As + 10240;
#pragma unroll
        for (int c = 0; c < 4; c++) {
            cp16(As + tid * 80 + c * 16, A + (size_t)(row0 + tid) * 256 + kc * 32 + c * 8);
            cp16(Bs + tid * 80 + c * 16, B + (size_t)(col0 + tid) * 256 + kc * 32 + c * 8);
        }
        cp_commit();
    };

    prefetch(0);
    prefetch(1);

    const int arow = lane & 15, acolh = (lane >> 4) * 8;
    const int bn   = (lane & 7) + (lane >> 4) * 8;
    const int bkh  = ((lane >> 3) & 1) * 8;

    for (int kc = 0; kc < 8; kc++) {
        if (kc + 1 < 8) cp_wait1(); else cp_wait0();
        __syncthreads();
        if (kc + 2 < 8) prefetch(kc + 2);

        int s = kc % 3;
        uint32_t As = smem_base + s * STG_BYTES;
        uint32_t Bs = As + 10240;

#pragma unroll
        for (int kk = 0; kk < 32; kk += 16) {
            uint32_t af[4][4];
#pragma unroll
            for (int i = 0; i < 4; i++) {
                uint32_t addr = As + (wm * 64 + i * 16 + arow) * 80 + (kk + acolh) * 2;
                ldsm4(af[i][0], af[i][1], af[i][2], af[i][3], addr);
            }
            uint32_t bf[8][2];
#pragma unroll
            for (int jp = 0; jp < 4; jp++) {
                uint32_t addr = Bs + (wn * 64 + jp * 16 + bn) * 80 + (kk + bkh) * 2;
                ldsm4(bf[2*jp][0], bf[2*jp][1], bf[2*jp+1][0], bf[2*jp+1][1], addr);
            }
#pragma unroll
            for (int i = 0; i < 4; i++)
#pragma unroll
                for (int j = 0; j < 8; j++)
                    mma16816h(acc[i][j], af[i], bf[j]);
        }
    }

    const int g = lane >> 2, tg = lane & 3;
#pragma unroll
    for (int j = 0; j < 8; j++) {
        int c = col0 + wn * 64 + j * 8 + 2 * tg;
        __half2 bb = __floats2half2_rn(bias[c], bias[c + 1]);
#pragma unroll
        for (int i = 0; i < 4; i++) {
            int r = row0 + wm * 64 + i * 16 + g;
            *reinterpret_cast<__half2*>(C + (size_t)r * 256 + c) =
                __hadd2(*reinterpret_cast<__half2*>(&acc[i][j][0]), bb);
            *reinterpret_cast<__half2*>(C + (size_t)(r + 8) * 256 + c) =
                __hadd2(*reinterpret_cast<__half2*>(&acc[i][j][1]), bb);
        }
    }
}

// ===================== prep kernels =====================
__device__ __forceinline__ uint2 cvt4(float4 x)
{
    union { __half2 h2[2]; uint2 u; } U;
    U.h2[0] = __floats2half2_rn(x.x, x.y);
    U.h2[1] = __floats2half2_rn(x.z, x.w);
    return U.u;
}

// fused prep_q + prep_w: blocks [0, 8192) -> q ; [8192, 11264) -> weights
__global__ void __launch_bounds__(256)
prep_qw(const float* __restrict__ a, const float* __restrict__ b,
        __half* __restrict__ o,
        const float* __restrict__ Wq, const float* __restrict__ Wk,
        const float* __restrict__ Wv, const float* __restrict__ Wrp,
        __half* __restrict__ ow)
{
    if (blockIdx.x < 8192) {
        int i = blockIdx.x * 256 + threadIdx.x;
        float4 x = reinterpret_cast<const float4*>(a)[i];
        float4 y = reinterpret_cast<const float4*>(b)[i];
        x.x += y.x; x.y += y.y; x.z += y.z; x.w += y.w;
        reinterpret_cast<uint2*>(o)[i] = cvt4(x);
        return;
    }
    int t = (blockIdx.x - 8192) * 256 + threadIdx.x;
    if (t < 589824) {
        int mat = t >> 16, idx = t & 65535;
        int n = idx >> 8, k = idx & 255;
        const float* W = (mat < 3) ? Wq + (size_t)mat * 65536
                       : (mat < 6) ? Wk + (size_t)(mat - 3) * 65536
                                   : Wv + (size_t)(mat - 6) * 65536;
        ow[(size_t)mat * 65536 + (size_t)n * 256 + k] = __float2half_rn(W[k * 256 + n]);
    } else {
        int idx = t - 589824;
        int n = idx / 768, k = idx - n * 768;
        ow[589824 + (size_t)n * 768 + k] = __float2half_rn(Wrp[(size_t)k * 256 + n]);
    }
}

// batched over branches: blockIdx.y = 0..2
__global__ void __launch_bounds__(256)
prep_kv_b(const float* __restrict__ f2, const float* __restrict__ f3, const float* __restrict__ f4,
          const float* __restrict__ p2, const float* __restrict__ p3, const float* __restrict__ p4,
          __half* __restrict__ abuf, int n4)
{
    int br = blockIdx.y;
    const float* f  = (br == 0) ? f2 : (br == 1) ? f3 : f4;
    const float* pe = (br == 0) ? p2 : (br == 1) ? p3 : p4;
    __half* ok = abuf + (size_t)(1 + br) * MTOT * 256;
    __half* ov = abuf + (size_t)(4 + br) * MTOT * 256;

    int i = blockIdx.x * 256 + threadIdx.x;
    if (i >= n4) return;
    float4 x = reinterpret_cast<const float4*>(f)[i];
    float4 y = reinterpret_cast<const float4*>(pe)[i];
    float4 k = make_float4(x.x + y.x, x.y + y.y, x.z + y.z, x.w + y.w);
    reinterpret_cast<uint2*>(ok)[i] = cvt4(k);
    reinterpret_cast<uint2*>(ov)[i] = cvt4(x);
}

// ===================== qsum reduce: inv[b,c] = 1 / sum over 64 row-blocks ====
__global__ void qsum_reduce_kernel()
{
    int b = blockIdx.x, c = blockIdx.y * 256 + threadIdx.x;
    float s = 0.f;
#pragma unroll 4
    for (int rb = 0; rb < 64; rb++)
        s += g_qsp[(size_t)(b * 64 + rb) * 768 + c];
    g_qs[b * 768 + c] = 1.f / s;
}

// ===================== ctx = softmax_c(k)^T v — register-blocked (R9) ========
__global__ void __launch_bounds__(256)
ctx_part_kernel()
{
    __shared__ float ks[32][40];
    __shared__ float vs[32][40];
    __shared__ float red[3][64][16];

    int x = blockIdx.x, branch = blockIdx.y;
    int chunk = x & 31, h = (x >> 5) & 7, b = x >> 8;
    int tid = threadIdx.x;
    int row = tid >> 3, c4 = (tid & 7) * 4;
    int g = tid >> 6, slot = tid & 63;
    int c0 = (slot >> 3) * 4, d0 = (slot & 7) * 4;

    float acc[4][4];
#pragma unroll
    for (int i = 0; i < 4; i++)
#pragma unroll
        for (int j = 0; j < 4; j++) acc[i][j] = 0.f;

    const size_t base = ((size_t)branch * MTOT + (size_t)b * SEQ + (size_t)chunk * 256) * DIM + h * HD;

    for (int t = 0; t < 8; t++) {
        const __half* kp = g_k16 + base + (size_t)(t * 32 + row) * DIM + c4;
        const __half* vp = g_v16 + base + (size_t)(t * 32 + row) * DIM + c4;
        uint2 ku = *reinterpret_cast<const uint2*>(kp);
        uint2 vu = *reinterpret_cast<const uint2*>(vp);
        float2 k01 = __half22float2(*reinterpret_cast<__half2*>(&ku.x));
        float2 k23 = __half22float2(*reinterpret_cast<__half2*>(&ku.y));
        float2 v01 = __half22float2(*reinterpret_cast<__half2*>(&vu.x));
        float2 v23 = __half22float2(*reinterpret_cast<__half2*>(&vu.y));

        float e0 = __expf(k01.x), e1 = __expf(k01.y);
        float e2 = __expf(k23.x), e3 = __expf(k23.y);
        float s = (e0 + e1) + (e2 + e3);
#pragma unroll
        for (int o = 1; o < 8; o <<= 1) s += __shfl_xor_sync(0xffffffffu, s, o);
        float inv = 1.f / s;

        __syncthreads();
        *reinterpret_cast<float4*>(&ks[row][c4]) = make_float4(e0*inv, e1*inv, e2*inv, e3*inv);
        *reinterpret_cast<float4*>(&vs[row][c4]) = make_float4(v01.x, v01.y, v23.x, v23.y);
        __syncthreads();

#pragma unroll
        for (int r8 = 0; r8 < 8; r8++) {
            int rr = g * 8 + r8;
            float4 kc = *reinterpret_cast<float4*>(&ks[rr][c0]);
            float4 vd = *reinterpret_cast<float4*>(&vs[rr][d0]);
            acc[0][0] += kc.x * vd.x; acc[0][1] += kc.x * vd.y;
            acc[0][2] += kc.x * vd.z; acc[0][3] += kc.x * vd.w;
            acc[1][0] += kc.y * vd.x; acc[1][1] += kc.y * vd.y;
            acc[1][2] += kc.y * vd.z; acc[1][3] += kc.y * vd.w;
            acc[2][0] += kc.z * vd.x; acc[2][1] += kc.z * vd.y;
            acc[2][2] += kc.z * vd.z; acc[2][3] += kc.z * vd.w;
            acc[3][0] += kc.w * vd.x; acc[3][1] += kc.w * vd.y;
            acc[3][2] += kc.w * vd.z; acc[3][3] += kc.w * vd.w;
        }
    }

    if (g > 0) {
#pragma unroll
        for (int i = 0; i < 4; i++)
            *reinterpret_cast<float4*>(&red[g-1][slot][i*4]) =
                make_float4(acc[i][0], acc[i][1], acc[i][2], acc[i][3]);
    }
    __syncthreads();
    if (g == 0) {
#pragma unroll
        for (int gg = 0; gg < 3; gg++)
#pragma unroll
            for (int i = 0; i < 4; i++) {
                float4 r4 = *reinterpret_cast<float4*>(&red[gg][slot][i*4]);
                acc[i][0] += r4.x; acc[i][1] += r4.y; acc[i][2] += r4.z; acc[i][3] += r4.w;
            }
        float* op = g_ctxp + ((size_t)branch * 1024 + x) * 1024;
#pragma unroll
        for (int i = 0; i < 4; i++)
            *reinterpret_cast<float4*>(op + (c0 + i) * 32 + d0) =
                make_float4(acc[i][0], acc[i][1], acc[i][2], acc[i][3]);
    }
}

// ===================== E[b][j][h24*32+c] = inv * sum_d ctx*wf ================
__global__ void __launch_bounds__(256)
ctxE_kernel(const __half* __restrict__ wf)
{
    __shared__ float cs[32][32];
    int h24 = blockIdx.x, b = blockIdx.y, j = threadIdx.x;
    int branch = h24 >> 3, hbr = h24 & 7;
    size_t pbase = (size_t)branch * 1024 + (size_t)b * 256 + hbr * 32;

    float local[4] = {0.f, 0.f, 0.f, 0.f};
    for (int ch = 0; ch < 32; ch++) {
        const float* cp = g_ctxp + (pbase + ch) * 1024 + j * 4;
#pragma unroll
        for (int u = 0; u < 4; u++) local[u] += cp[u];
    }
#pragma unroll
    for (int u = 0; u < 4; u++) {
        int idx = j * 4 + u;
        cs[idx >> 5][idx & 31] = local[u];
    }
    __syncthreads();

    float wd[32];
#pragma unroll
    for (int d = 0; d < 32; d++)
        wd[d] = __half2float(wf[(size_t)j * 768 + h24 * 32 + d]);

    const float* invp = g_qs + b * 768 + h24 * 32;
    __half* ep = g_E + ((size_t)b * 256 + j) * 768 + h24 * 32;
#pragma unroll
    for (int c = 0; c < 32; c++) {
        float a = 0.f;
#pragma unroll
        for (int d = 0; d < 32; d++) a += cs[c][d] * wd[d];
        ep[c] = __float2half_rn(a * invp[c]);
    }
}

// ===================== launcher =====================
extern "C" void kernel_launch(void* const* d_in, const int* in_sizes, int n_in,
                              void* d_out, int out_size)
{
    const float* f[4]   = {(const float*)d_in[0], (const float*)d_in[1],
                           (const float*)d_in[2], (const float*)d_in[3]};
    const float* fpe[4] = {(const float*)d_in[4], (const float*)d_in[5],
                           (const float*)d_in[6], (const float*)d_in[7]};
    const float* Wq  = (const float*)d_in[8];
    const float* bq  = (const float*)d_in[9];
    const float* Wk  = (const float*)d_in[10];
    const float* bk  = (const float*)d_in[11];
    const float* Wv  = (const float*)d_in[12];
    const float* bv  = (const float*)d_in[13];
    const float* Wrp = (const float*)d_in[14];
    const float* brp = (const float*)d_in[15];
    float* out = (float*)d_out;

    cudaFuncSetAttribute(gemm_expq,   cudaFuncAttributeMaxDynamicSharedMemorySize, GEMM_SMEM);
    cudaFuncSetAttribute(gemm_f32out, cudaFuncAttributeMaxDynamicSharedMemorySize, GEMM_SMEM);
    cudaFuncSetAttribute(gemm_kv,     cudaFuncAttributeMaxDynamicSharedMemorySize, GEMM_SMEM);

    __half *abuf, *wbuf, *q16, *E;
    cudaGetSymbolAddress((void**)&abuf, g_a);
    cudaGetSymbolAddress((void**)&wbuf, g_w);
    cudaGetSymbolAddress((void**)&q16,  g_q16);
    cudaGetSymbolAddress((void**)&E,    g_E);

    const int n4 = MTOT * DIM / 4;
    const int pb = n4 / 256;          // 8192

    __half* wq = wbuf;                    // [768][256]
    __half* wk = wbuf + 196608;           // 3 x [256][256], then wv 3 x
    __half* wf = wbuf + 589824;           // [256][768]

    // launches 1-3
    prep_qw<<<8192 + 3072, 256>>>(f[0], fpe[0], abuf, Wq, Wk, Wv, Wrp, wbuf);
    prep_kv_b<<<dim3(pb, 3), 256>>>(f[1], f[2], f[3], fpe[1], fpe[2], fpe[3], abuf, n4);
    gemm_expq<<<dim3(6, MTOT/128, 1), 256, GEMM_SMEM>>>(abuf, 256, wq, 256, bq, q16, 768, 8);

    // launch 4 (ncu slot): fp16-acc k/v GEMM — CTA tile 128x128, N=256 -> grid.x=2
    gemm_kv<<<dim3(2, MTOT/128, 6), 128, GEMM_SMEM>>>(abuf, wk, bk, bv);

    // ctx partials for all branches
    ctx_part_kernel<<<dim3(BB * NH * CCH, 3), 256>>>();

    // q-softmax normalization constants
    qsum_reduce_kernel<<<dim3(BB, 3), 256>>>();

    // effective final weights (ctx reduce + Wrp fold + inv fold)
    ctxE_kernel<<<dim3(24, BB), 256>>>(wf);

    // out = expq @ E[b] + brp
    gemm_f32out<<<dim3(2, MTOT/128, 1), 256, GEMM_SMEM>>>(q16, 768, E, 768, (size_t)256*768,
                                                          brp, out, 256, 24);
}

// round 14
// speedup vs baseline: 1.1367x; 1.1367x over previous
#include <cuda_runtime.h>
#include <cuda_fp16.h>
#include <cstdint>

#define BB   4
#define SEQ  8192
#define DIM  256
#define NH   8
#define HD   32
#define MTOT (BB*SEQ)        // 32768
#define CCH  32

// ===================== scratch (device globals) =====================
__device__ __half g_a[7ull * MTOT * 256];        // fp16 activations: q_in, k2..k4, v2..v4
__device__ __half g_q16[(size_t)MTOT * 768];     // fp16 expq = exp(q)/32
__device__ __half g_w[786432];                   // fp16 weights: wq|wk,wv|wf(256x768)
__device__ __half g_E[4ull * 256 * 768];         // per-batch effective final weights (inv folded)
__device__ __half g_k16[3ull * MTOT * DIM];
__device__ __half g_v16[3ull * MTOT * DIM];
__device__ float g_ctxp[3ull * BB * NH * CCH * HD * HD];
__device__ float g_qs  [BB * 768];               // 1 / sum(exp(q)/32)
__device__ float g_qsp [256 * 768];              // per-row-block column partials

// ===================== helpers =====================
__device__ __forceinline__ uint32_t smem_u32(const void* p){
    uint32_t a;
    asm("{ .reg .u64 t; cvta.to.shared.u64 t, %1; cvt.u32.u64 %0, t; }" : "=r"(a) : "l"(p));
    return a;
}
__device__ __forceinline__ void cp16(uint32_t dst, const void* src){
    asm volatile("cp.async.cg.shared.global [%0], [%1], 16;" :: "r"(dst), "l"(src) : "memory");
}
__device__ __forceinline__ void cp_commit(){ asm volatile("cp.async.commit_group;" ::: "memory"); }
__device__ __forceinline__ void cp_wait1(){ asm volatile("cp.async.wait_group 1;" ::: "memory"); }
__device__ __forceinline__ void cp_wait0(){ asm volatile("cp.async.wait_group 0;" ::: "memory"); }

__device__ __forceinline__ void ldsm4(uint32_t& r0, uint32_t& r1, uint32_t& r2, uint32_t& r3, uint32_t addr){
    asm volatile("ldmatrix.sync.aligned.m8n8.x4.shared.b16 {%0,%1,%2,%3}, [%4];"
        : "=r"(r0), "=r"(r1), "=r"(r2), "=r"(r3) : "r"(addr));
}
__device__ __forceinline__ void mma16816(float* d, const uint32_t* a, const uint32_t* b){
    asm volatile("mma.sync.aligned.m16n8k16.row.col.f32.f16.f16.f32 "
        "{%0,%1,%2,%3}, {%4,%5,%6,%7}, {%8,%9}, {%0,%1,%2,%3};"
        : "+f"(d[0]), "+f"(d[1]), "+f"(d[2]), "+f"(d[3])
        : "r"(a[0]), "r"(a[1]), "r"(a[2]), "r"(a[3]), "r"(b[0]), "r"(b[1]));
}

// ===================== GEMM core: 128x128 CTA tile, fp32 acc (R9 config) =====
#define STG_BYTES 20480
#define GEMM_SMEM (3 * STG_BYTES)

#define GEMM_BODY(A, lda, B, ldb, nkc, ROW0, COL0)                              \
    const int lane = tid & 31, wid = tid >> 5;                                  \
    const int wm = wid >> 2, wn = wid & 3;                                      \
    const int row0 = (ROW0);                                                    \
    const int col0 = (COL0);                                                    \
    float acc[4][4][4];                                                         \
    _Pragma("unroll") for (int i = 0; i < 4; i++)                               \
    _Pragma("unroll") for (int j = 0; j < 4; j++)                               \
    _Pragma("unroll") for (int v = 0; v < 4; v++) acc[i][j][v] = 0.f;           \
    const uint32_t smem_base = smem_u32(smem);                                  \
    const int ch0 = tid * 2;                                                    \
    auto prefetch = [&](int kc) {                                               \
        int s = kc % 3;                                                         \
        uint32_t As = smem_base + s * STG_BYTES;                                \
        uint32_t Bs = As + 10240;                                               \
        _Pragma("unroll") for (int t = 0; t < 2; t++) {                         \
            int ch = ch0 + t;                                                   \
            int r = ch >> 2, c = ch & 3;                                        \
            cp16(As + r * 80 + c * 16, A + (size_t)(row0 + r) * lda + kc * 32 + c * 8); \
            cp16(Bs + r * 80 + c * 16, B + (size_t)(col0 + r) * ldb + kc * 32 + c * 8); \
        }                                                                       \
        cp_commit();                                                            \
    };                                                                          \
    prefetch(0);                                                                \
    if (nkc > 1) prefetch(1);                                                   \
    const int arow = lane & 15, acolh = (lane >> 4) * 8;                        \
    const int bn   = (lane & 7) + (lane >> 4) * 8;                              \
    const int bkh  = ((lane >> 3) & 1) * 8;                                     \
    for (int kc = 0; kc < nkc; kc++) {                                          \
        if (kc + 1 < nkc) cp_wait1(); else cp_wait0();                          \
        __syncthreads();                                                        \
        if (kc + 2 < nkc) prefetch(kc + 2);                                     \
        int s = kc % 3;                                                         \
        uint32_t As = smem_base + s * STG_BYTES;                                \
        uint32_t Bs = As + 10240;                                               \
        _Pragma("unroll") for (int kk = 0; kk < 32; kk += 16) {                 \
            uint32_t af[4][4];                                                  \
            _Pragma("unroll") for (int i = 0; i < 4; i++) {                     \
                uint32_t addr = As + (wm * 64 + i * 16 + arow) * 80 + (kk + acolh) * 2; \
                ldsm4(af[i][0], af[i][1], af[i][2], af[i][3], addr);            \
            }                                                                   \
            uint32_t bf[4][2];                                                  \
            _Pragma("unroll") for (int jp = 0; jp < 2; jp++) {                  \
                uint32_t addr = Bs + (wn * 32 + jp * 16 + bn) * 80 + (kk + bkh) * 2; \
                ldsm4(bf[2*jp][0], bf[2*jp][1], bf[2*jp+1][0], bf[2*jp+1][1], addr); \
            }                                                                   \
            _Pragma("unroll") for (int i = 0; i < 4; i++)                       \
            _Pragma("unroll") for (int j = 0; j < 4; j++)                       \
                mma16816(acc[i][j], af[i], bf[j]);                              \
        }                                                                       \
    }

// qall GEMM with fused exp + column partial sums (R9 config).
__global__ void __launch_bounds__(256, 2)
gemm_expq(const __half* __restrict__ Ag, int lda,
          const __half* __restrict__ Bg, int ldb,
          const float* __restrict__ bias, __half* __restrict__ C, int N, int KH)
{
    extern __shared__ __align__(16) char smem[];
    const int tid = threadIdx.x;
    GEMM_BODY(Ag, lda, Bg, ldb, KH, blockIdx.y * 128, blockIdx.x * 128)

    __syncthreads();
    float* red = reinterpret_cast<float*>(smem);      // [16][128]
    const int g = lane >> 2, tg = lane & 3;
    float bb0[4], bb1[4];
#pragma unroll
    for (int j = 0; j < 4; j++) {
        int c = col0 + wn * 32 + j * 8 + 2 * tg;
        bb0[j] = bias[c]; bb1[j] = bias[c + 1];
    }
    float cs0[4] = {0.f,0.f,0.f,0.f}, cs1[4] = {0.f,0.f,0.f,0.f};
#pragma unroll
    for (int i = 0; i < 4; i++) {
        int r = row0 + wm * 64 + i * 16 + g;
#pragma unroll
        for (int j = 0; j < 4; j++) {
            int c = col0 + wn * 32 + j * 8 + 2 * tg;
            float e0 = __expf(acc[i][j][0] + bb0[j]) * 0.03125f;
            float e1 = __expf(acc[i][j][1] + bb1[j]) * 0.03125f;
            float e2 = __expf(acc[i][j][2] + bb0[j]) * 0.03125f;
            float e3 = __expf(acc[i][j][3] + bb1[j]) * 0.03125f;
            *reinterpret_cast<__half2*>(C + (size_t)r * N + c)       = __floats2half2_rn(e0, e1);
            *reinterpret_cast<__half2*>(C + (size_t)(r + 8) * N + c) = __floats2half2_rn(e2, e3);
            cs0[j] += e0 + e2;
            cs1[j] += e1 + e3;
        }
    }
#pragma unroll
    for (int j = 0; j < 4; j++) {
        int lc = wn * 32 + j * 8 + 2 * tg;
        red[(wm * 8 + g) * 128 + lc]     = cs0[j];
        red[(wm * 8 + g) * 128 + lc + 1] = cs1[j];
    }
    __syncthreads();
    if (tid < 128) {
        float s = 0.f;
#pragma unroll
        for (int u = 0; u < 16; u++) s += red[u * 128 + tid];
        g_qsp[(size_t)blockIdx.y * 768 + col0 + tid] = s;
    }
}

// fp32-output GEMM with per-batch B (final): B += (blockIdx.y>>6)*bstride
__global__ void __launch_bounds__(256, 2)
gemm_f32out(const __half* __restrict__ Ag, int lda,
            const __half* __restrict__ Bg0, int ldb, size_t bstride,
            const float* __restrict__ bias, float* __restrict__ C, int N, int KH)
{
    extern __shared__ __align__(16) char smem[];
    const int tid = threadIdx.x;
    const __half* Bg = Bg0 + (size_t)(blockIdx.y >> 6) * bstride;
    GEMM_BODY(Ag, lda, Bg, ldb, KH, blockIdx.y * 128, blockIdx.x * 128)

    const int g = lane >> 2, tg = lane & 3;
    float2 bb[4];
#pragma unroll
    for (int j = 0; j < 4; j++) {
        int c = col0 + wn * 32 + j * 8 + 2 * tg;
        bb[j] = make_float2(bias[c], bias[c + 1]);
    }
#pragma unroll
    for (int i = 0; i < 4; i++) {
        int r = row0 + wm * 64 + i * 16 + g;
#pragma unroll
        for (int j = 0; j < 4; j++) {
            int c = col0 + wn * 32 + j * 8 + 2 * tg;
            *reinterpret_cast<float2*>(C + (size_t)r * N + c) =
                make_float2(acc[i][j][0] + bb[j].x, acc[i][j][1] + bb[j].y);
            *reinterpret_cast<float2*>(C + (size_t)(r + 8) * N + c) =
                make_float2(acc[i][j][2] + bb[j].x, acc[i][j][3] + bb[j].y);
        }
    }
}

// batched k/v GEMM (R9 config): z = 0..5 -> branch = z%3, kv = z/3; fp16 out, fp32 acc
__global__ void __launch_bounds__(256, 2)
gemm_kv(const __half* __restrict__ abuf, const __half* __restrict__ wkv,
        const float* __restrict__ bk, const float* __restrict__ bv)
{
    extern __shared__ __align__(16) char smem[];
    const int tid = threadIdx.x;
    const int z = blockIdx.z;
    const int branch = z % 3, kv = z / 3;
    const __half* Ag = abuf + (size_t)(1 + branch + 3 * kv) * MTOT * 256;
    const __half* Bg = wkv + (size_t)(3 * kv + branch) * 65536;
    const float* bias = (kv ? bv : bk) + branch * 256;
    __half* C = (kv ? g_v16 : g_k16) + (size_t)branch * MTOT * 256;

    GEMM_BODY(Ag, 256, Bg, 256, 8, blockIdx.y * 128, blockIdx.x * 128)

    const int g = lane >> 2, tg = lane & 3;
    float2 bb[4];
#pragma unroll
    for (int j = 0; j < 4; j++) {
        int c = col0 + wn * 32 + j * 8 + 2 * tg;
        bb[j] = make_float2(bias[c], bias[c + 1]);
    }
#pragma unroll
    for (int i = 0; i < 4; i++) {
        int r = row0 + wm * 64 + i * 16 + g;
#pragma unroll
        for (int j = 0; j < 4; j++) {
            int c = col0 + wn * 32 + j * 8 + 2 * tg;
            *reinterpret_cast<__half2*>(C + (size_t)r * 256 + c) =
                __floats2half2_rn(acc[i][j][0] + bb[j].x, acc[i][j][1] + bb[j].y);
            *reinterpret_cast<__half2*>(C + (size_t)(r + 8) * 256 + c) =
                __floats2half2_rn(acc[i][j][2] + bb[j].x, acc[i][j][3] + bb[j].y);
        }
    }
}

// ===================== prep kernels =====================
__device__ __forceinline__ uint2 cvt4(float4 x)
{
    union { __half2 h2[2]; uint2 u; } U;
    U.h2[0] = __floats2half2_rn(x.x, x.y);
    U.h2[1] = __floats2half2_rn(x.z, x.w);
    return U.u;
}

// fused prep_q + prep_w: blocks [0, 8192) -> q ; [8192, 11264) -> weights
__global__ void __launch_bounds__(256)
prep_qw(const float* __restrict__ a, const float* __restrict__ b,
        __half* __restrict__ o,
        const float* __restrict__ Wq, const float* __restrict__ Wk,
        const float* __restrict__ Wv, const float* __restrict__ Wrp,
        __half* __restrict__ ow)
{
    if (blockIdx.x < 8192) {
        int i = blockIdx.x * 256 + threadIdx.x;
        float4 x = reinterpret_cast<const float4*>(a)[i];
        float4 y = reinterpret_cast<const float4*>(b)[i];
        x.x += y.x; x.y += y.y; x.z += y.z; x.w += y.w;
        reinterpret_cast<uint2*>(o)[i] = cvt4(x);
        return;
    }
    int t = (blockIdx.x - 8192) * 256 + threadIdx.x;
    if (t < 589824) {
        int mat = t >> 16, idx = t & 65535;
        int n = idx >> 8, k = idx & 255;
        const float* W = (mat < 3) ? Wq + (size_t)mat * 65536
                       : (mat < 6) ? Wk + (size_t)(mat - 3) * 65536
                                   : Wv + (size_t)(mat - 6) * 65536;
        ow[(size_t)mat * 65536 + (size_t)n * 256 + k] = __float2half_rn(W[k * 256 + n]);
    } else {
        int idx = t - 589824;
        int n = idx / 768, k = idx - n * 768;
        ow[589824 + (size_t)n * 768 + k] = __float2half_rn(Wrp[(size_t)k * 256 + n]);
    }
}

// batched over branches: blockIdx.y = 0..2
__global__ void __launch_bounds__(256)
prep_kv_b(const float* __restrict__ f2, const float* __restrict__ f3, const float* __restrict__ f4,
          const float* __restrict__ p2, const float* __restrict__ p3, const float* __restrict__ p4,
          __half* __restrict__ abuf, int n4)
{
    int br = blockIdx.y;
    const float* f  = (br == 0) ? f2 : (br == 1) ? f3 : f4;
    const float* pe = (br == 0) ? p2 : (br == 1) ? p3 : p4;
    __half* ok = abuf + (size_t)(1 + br) * MTOT * 256;
    __half* ov = abuf + (size_t)(4 + br) * MTOT * 256;

    int i = blockIdx.x * 256 + threadIdx.x;
    if (i >= n4) return;
    float4 x = reinterpret_cast<const float4*>(f)[i];
    float4 y = reinterpret_cast<const float4*>(pe)[i];
    float4 k = make_float4(x.x + y.x, x.y + y.y, x.z + y.z, x.w + y.w);
    reinterpret_cast<uint2*>(ok)[i] = cvt4(k);
    reinterpret_cast<uint2*>(ov)[i] = cvt4(x);
}

// ===================== qsum reduce: inv[b,c] = 1 / sum over 64 row-blocks ====
__global__ void qsum_reduce_kernel()
{
    int b = blockIdx.x, c = blockIdx.y * 256 + threadIdx.x;
    float s = 0.f;
#pragma unroll 4
    for (int rb = 0; rb < 64; rb++)
        s += g_qsp[(size_t)(b * 64 + rb) * 768 + c];
    g_qs[b * 768 + c] = 1.f / s;
}

// ===================== ctx = softmax_c(k)^T v — register-blocked (R9) ========
__global__ void __launch_bounds__(256)
ctx_part_kernel()
{
    __shared__ float ks[32][40];
    __shared__ float vs[32][40];
    __shared__ float red[3][64][16];

    int x = blockIdx.x, branch = blockIdx.y;
    int chunk = x & 31, h = (x >> 5) & 7, b = x >> 8;
    int tid = threadIdx.x;
    int row = tid >> 3, c4 = (tid & 7) * 4;
    int g = tid >> 6, slot = tid & 63;
    int c0 = (slot >> 3) * 4, d0 = (slot & 7) * 4;

    float acc[4][4];
#pragma unroll
    for (int i = 0; i < 4; i++)
#pragma unroll
        for (int j = 0; j < 4; j++) acc[i][j] = 0.f;

    const size_t base = ((size_t)branch * MTOT + (size_t)b * SEQ + (size_t)chunk * 256) * DIM + h * HD;

    for (int t = 0; t < 8; t++) {
        const __half* kp = g_k16 + base + (size_t)(t * 32 + row) * DIM + c4;
        const __half* vp = g_v16 + base + (size_t)(t * 32 + row) * DIM + c4;
        uint2 ku = *reinterpret_cast<const uint2*>(kp);
        uint2 vu = *reinterpret_cast<const uint2*>(vp);
        float2 k01 = __half22float2(*reinterpret_cast<__half2*>(&ku.x));
        float2 k23 = __half22float2(*reinterpret_cast<__half2*>(&ku.y));
        float2 v01 = __half22float2(*reinterpret_cast<__half2*>(&vu.x));
        float2 v23 = __half22float2(*reinterpret_cast<__half2*>(&vu.y));

        float e0 = __expf(k01.x), e1 = __expf(k01.y);
        float e2 = __expf(k23.x), e3 = __expf(k23.y);
        float s = (e0 + e1) + (e2 + e3);
#pragma unroll
        for (int o = 1; o < 8; o <<= 1) s += __shfl_xor_sync(0xffffffffu, s, o);
        float inv = 1.f / s;

        __syncthreads();
        *reinterpret_cast<float4*>(&ks[row][c4]) = make_float4(e0*inv, e1*inv, e2*inv, e3*inv);
        *reinterpret_cast<float4*>(&vs[row][c4]) = make_float4(v01.x, v01.y, v23.x, v23.y);
        __syncthreads();

#pragma unroll
        for (int r8 = 0; r8 < 8; r8++) {
            int rr = g * 8 + r8;
            float4 kc = *reinterpret_cast<float4*>(&ks[rr][c0]);
            float4 vd = *reinterpret_cast<float4*>(&vs[rr][d0]);
            acc[0][0] += kc.x * vd.x; acc[0][1] += kc.x * vd.y;
            acc[0][2] += kc.x * vd.z; acc[0][3] += kc.x * vd.w;
            acc[1][0] += kc.y * vd.x; acc[1][1] += kc.y * vd.y;
            acc[1][2] += kc.y * vd.z; acc[1][3] += kc.y * vd.w;
            acc[2][0] += kc.z * vd.x; acc[2][1] += kc.z * vd.y;
            acc[2][2] += kc.z * vd.z; acc[2][3] += kc.z * vd.w;
            acc[3][0] += kc.w * vd.x; acc[3][1] += kc.w * vd.y;
            acc[3][2] += kc.w * vd.z; acc[3][3] += kc.w * vd.w;
        }
    }

    if (g > 0) {
#pragma unroll
        for (int i = 0; i < 4; i++)
            *reinterpret_cast<float4*>(&red[g-1][slot][i*4]) =
                make_float4(acc[i][0], acc[i][1], acc[i][2], acc[i][3]);
    }
    __syncthreads();
    if (g == 0) {
#pragma unroll
        for (int gg = 0; gg < 3; gg++)
#pragma unroll
            for (int i = 0; i < 4; i++) {
                float4 r4 = *reinterpret_cast<float4*>(&red[gg][slot][i*4]);
                acc[i][0] += r4.x; acc[i][1] += r4.y; acc[i][2] += r4.z; acc[i][3] += r4.w;
            }
        float* op = g_ctxp + ((size_t)branch * 1024 + x) * 1024;
#pragma unroll
        for (int i = 0; i < 4; i++)
            *reinterpret_cast<float4*>(op + (c0 + i) * 32 + d0) =
                make_float4(acc[i][0], acc[i][1], acc[i][2], acc[i][3]);
    }
}

// ===================== E[b][j][h24*32+c] = inv * sum_d ctx*wf ================
__global__ void __launch_bounds__(256)
ctxE_kernel(const __half* __restrict__ wf)
{
    __shared__ float cs[32][32];
    int h24 = blockIdx.x, b = blockIdx.y, j = threadIdx.x;
    int branch = h24 >> 3, hbr = h24 & 7;
    size_t pbase = (size_t)branch * 1024 + (size_t)b * 256 + hbr * 32;

    float local[4] = {0.f, 0.f, 0.f, 0.f};
    for (int ch = 0; ch < 32; ch++) {
        const float* cp = g_ctxp + (pbase + ch) * 1024 + j * 4;
#pragma unroll
        for (int u = 0; u < 4; u++) local[u] += cp[u];
    }
#pragma unroll
    for (int u = 0; u < 4; u++) {
        int idx = j * 4 + u;
        cs[idx >> 5][idx & 31] = local[u];
    }
    __syncthreads();

    float wd[32];
#pragma unroll
    for (int d = 0; d < 32; d++)
        wd[d] = __half2float(wf[(size_t)j * 768 + h24 * 32 + d]);

    const float* invp = g_qs + b * 768 + h24 * 32;
    __half* ep = g_E + ((size_t)b * 256 + j) * 768 + h24 * 32;
#pragma unroll
    for (int c = 0; c < 32; c++) {
        float a = 0.f;
#pragma unroll
        for (int d = 0; d < 32; d++) a += cs[c][d] * wd[d];
        ep[c] = __float2half_rn(a * invp[c]);
    }
}

// ===================== launcher (two-stream fork-join, capture-safe) =========
extern "C" void kernel_launch(void* const* d_in, const int* in_sizes, int n_in,
                              void* d_out, int out_size)
{
    const float* f[4]   = {(const float*)d_in[0], (const float*)d_in[1],
                           (const float*)d_in[2], (const float*)d_in[3]};
    const float* fpe[4] = {(const float*)d_in[4], (const float*)d_in[5],
                           (const float*)d_in[6], (const float*)d_in[7]};
    const float* Wq  = (const float*)d_in[8];
    const float* bq  = (const float*)d_in[9];
    const float* Wk  = (const float*)d_in[10];
    const float* bk  = (const float*)d_in[11];
    const float* Wv  = (const float*)d_in[12];
    const float* bv  = (const float*)d_in[13];
    const float* Wrp = (const float*)d_in[14];
    const float* brp = (const float*)d_in[15];
    float* out = (float*)d_out;

    cudaFuncSetAttribute(gemm_expq,   cudaFuncAttributeMaxDynamicSharedMemorySize, GEMM_SMEM);
    cudaFuncSetAttribute(gemm_f32out, cudaFuncAttributeMaxDynamicSharedMemorySize, GEMM_SMEM);
    cudaFuncSetAttribute(gemm_kv,     cudaFuncAttributeMaxDynamicSharedMemorySize, GEMM_SMEM);

    __half *abuf, *wbuf, *q16, *E;
    cudaGetSymbolAddress((void**)&abuf, g_a);
    cudaGetSymbolAddress((void**)&wbuf, g_w);
    cudaGetSymbolAddress((void**)&q16,  g_q16);
    cudaGetSymbolAddress((void**)&E,    g_E);

    const int n4 = MTOT * DIM / 4;
    const int pb = n4 / 256;          // 8192

    __half* wq = wbuf;                    // [768][256]
    __half* wk = wbuf + 196608;           // 3 x [256][256], then wv 3 x
    __half* wf = wbuf + 589824;           // [256][768]

    // second stream + events (created once; host-side resources only)
    static cudaStream_t s2 = nullptr;
    static cudaEvent_t eFork = nullptr, eW = nullptr, eCtx = nullptr;
    if (s2 == nullptr) {
        cudaStreamCreateWithFlags(&s2, cudaStreamNonBlocking);
        cudaEventCreateWithFlags(&eFork, cudaEventDisableTiming);
        cudaEventCreateWithFlags(&eW,    cudaEventDisableTiming);
        cudaEventCreateWithFlags(&eCtx,  cudaEventDisableTiming);
    }

    // ---- fork: s2 branches off the main (capture) stream ----
    cudaEventRecord(eFork, 0);
    cudaStreamWaitEvent(s2, eFork, 0);

    // s2: kv-activation prep (independent of weights)
    prep_kv_b<<<dim3(pb, 3), 256, 0, s2>>>(f[1], f[2], f[3], fpe[1], fpe[2], fpe[3], abuf, n4);

    // s0: q-activation + all weights
    prep_qw<<<8192 + 3072, 256>>>(f[0], fpe[0], abuf, Wq, Wk, Wv, Wrp, wbuf);
    cudaEventRecord(eW, 0);

    // s0: qall GEMM with fused exp + column sums, then normalization constants
    gemm_expq<<<dim3(6, MTOT/128, 1), 256, GEMM_SMEM>>>(abuf, 256, wq, 256, bq, q16, 768, 8);
    qsum_reduce_kernel<<<dim3(BB, 3), 256>>>();

    // s2: kv GEMMs (need weights) then ctx partials
    cudaStreamWaitEvent(s2, eW, 0);
    gemm_kv<<<dim3(2, MTOT/128, 6), 256, GEMM_SMEM, s2>>>(abuf, wk, bk, bv);
    ctx_part_kernel<<<dim3(BB * NH * CCH, 3), 256, 0, s2>>>();
    cudaEventRecord(eCtx, s2);

    // ---- join: main stream waits for the kv-chain ----
    cudaStreamWaitEvent(0, eCtx, 0);

    // effective final weights (ctx reduce + Wrp fold + inv fold)
    ctxE_kernel<<<dim3(24, BB), 256>>>(wf);

    // out = expq @ E[b] + brp
    gemm_f32out<<<dim3(2, MTOT/128, 1), 256, GEMM_SMEM>>>(q16, 768, E, 768, (size_t)256*768,
                                                          brp, out, 256, 24);
}